// round 15
// baseline (speedup 1.0000x reference)
#include <cuda_runtime.h>
#include <cuda_fp16.h>
#include <math.h>

#define BB 1024
#define TT 512
#define II 4
#define HH 32
#define GG 96   // 3*H

typedef unsigned long long u64;

// Scratch sequence buffers (allocation-free rule: __device__ globals).
__device__ __half g_h1 [(size_t)BB * TT * 2 * HH];   // layer0 out (fp16)
__device__ u64    g_xg [(size_t)2 * BB * TT * HH];   // layer1 gates packed (r,z,n,pad)
__device__ float  g_out[(size_t)BB * TT * 2 * HH];   // layer1 out (fp32)

__device__ __forceinline__ u64 fma2(u64 a, u64 b, u64 c) {
    u64 d;
    asm("fma.rn.f32x2 %0, %1, %2, %3;" : "=l"(d) : "l"(a), "l"(b), "l"(c));
    return d;
}
__device__ __forceinline__ float sum2(u64 v) {
    float lo, hi;
    asm("mov.b64 {%0, %1}, %2;" : "=f"(lo), "=f"(hi) : "l"(v));
    return lo + hi;
}
__device__ __forceinline__ u64 pack2(float lo, float hi) {
    u64 d;
    asm("mov.b64 %0, {%1, %2};" : "=l"(d) : "f"(lo), "f"(hi));
    return d;
}
// HW tanh: single MUFU op
__device__ __forceinline__ float ftanh(float x) {
    float y;
    asm("tanh.approx.f32 %0, %1;" : "=f"(y) : "f"(x));
    return y;
}
// sigmoid(x) = 0.5*tanh(0.5x) + 0.5
__device__ __forceinline__ float fsig(float x) {
    return fmaf(0.5f, ftanh(0.5f * x), 0.5f);
}
__device__ __forceinline__ __half2 u64_to_h2(u64 v) {
    float lo, hi;
    asm("mov.b64 {%0, %1}, %2;" : "=f"(lo), "=f"(hi) : "l"(v));
    return __floats2half2_rn(lo, hi);
}
__device__ __forceinline__ float h2sum(__half2 v) {
    return __low2float(v) + __high2float(v);
}
#define H2(u) (*(const __half2*)&(u))

// ---------------------------------------------------------------------------
// Layer 0: one warp handles TWO sequences (b0, b0+1) of the same direction.
// HFMA2 MACs; weights shared across the pair; HW tanh; prefetch depth 2.
// grid: (B/4, 2), block 64 (2 warps).
// ---------------------------------------------------------------------------
__global__ void __launch_bounds__(64) gru_l0(
    const float* __restrict__ x,      // [B,T,4]
    const float* __restrict__ w_ih,   // [2,96,4]
    const float* __restrict__ w_hh,   // [2,96,32]
    const float* __restrict__ b_ih,   // [2,96]
    const float* __restrict__ b_hh)   // [2,96]
{
    __shared__ __align__(16) __half sh[2][2][2][32];  // [warp][seq][parity][lane]

    const int warp = threadIdx.x >> 5;
    const int j    = threadIdx.x & 31;
    const int dir  = blockIdx.y;
    const int b0   = blockIdx.x * 4 + warp * 2;

    const u64* w64 = (const u64*)w_hh;
    __half2 wr[16], wz[16], wn[16];
    {
        const int rb = (dir * GG + j) * 16;
        const int zb = (dir * GG + 32 + j) * 16;
        const int nb = (dir * GG + 64 + j) * 16;
        #pragma unroll
        for (int m = 0; m < 16; m++) {
            wr[m] = u64_to_h2(w64[rb + m]);
            wz[m] = u64_to_h2(w64[zb + m]);
            wn[m] = u64_to_h2(w64[nb + m]);
        }
    }
    const u64* wi64 = (const u64*)w_ih;
    const u64 wrA = wi64[(dir * GG + j) * 2],      wrB = wi64[(dir * GG + j) * 2 + 1];
    const u64 wzA = wi64[(dir * GG + 32 + j) * 2], wzB = wi64[(dir * GG + 32 + j) * 2 + 1];
    const u64 wnA = wi64[(dir * GG + 64 + j) * 2], wnB = wi64[(dir * GG + 64 + j) * 2 + 1];

    const u64 br2 = pack2(b_ih[dir * GG + j]      + b_hh[dir * GG + j],      0.0f);
    const u64 bz2 = pack2(b_ih[dir * GG + 32 + j] + b_hh[dir * GG + 32 + j], 0.0f);
    const u64 bx2 = pack2(b_ih[dir * GG + 64 + j], 0.0f);
    const float bhn = b_hh[dir * GG + 64 + j];

    float h0 = 0.0f, h1 = 0.0f;
    const int tstep = dir ? -1 : 1;
    int t = dir ? (TT - 1) : 0;

    const ulonglong2* xA = (const ulonglong2*)(x + (size_t)b0 * TT * II);
    const ulonglong2* xB = xA + TT;
    __half* oA = g_h1 + (size_t)b0 * TT * 2 * HH + dir * HH + j;
    __half* oB = oA + (size_t)TT * 2 * HH;

    ulonglong2 a0 = xA[t],           c0 = xB[t];
    ulonglong2 a1 = xA[t + tstep],   c1 = xB[t + tstep];

    for (int s = 0; s < TT; ++s, t += tstep) {
        int tp = t + 2 * tstep;
        tp = (tp < 0) ? 0 : ((tp >= TT) ? (TT - 1) : tp);
        const ulonglong2 a2 = xA[tp];
        const ulonglong2 c2 = xB[tp];

        const int par = s & 1;
        sh[warp][0][par][j] = __float2half(h0);
        sh[warp][1][par][j] = __float2half(h1);
        __syncwarp();

        const u64 rin0 = fma2(wrA, a0.x, fma2(wrB, a0.y, br2));
        const u64 zin0 = fma2(wzA, a0.x, fma2(wzB, a0.y, bz2));
        const u64 xin0 = fma2(wnA, a0.x, fma2(wnB, a0.y, bx2));
        const u64 rin1 = fma2(wrA, c0.x, fma2(wrB, c0.y, br2));
        const u64 zin1 = fma2(wzA, c0.x, fma2(wzB, c0.y, bz2));
        const u64 xin1 = fma2(wnA, c0.x, fma2(wnB, c0.y, bx2));

        __half2 rA0, rA1, zA0, zA1, nA0, nA1;
        __half2 rB0, rB1, zB0, zB1, nB0, nB1;
        rA0 = rA1 = zA0 = zA1 = nA0 = nA1 = __floats2half2_rn(0.0f, 0.0f);
        rB0 = rB1 = zB0 = zB1 = nB0 = nB1 = __floats2half2_rn(0.0f, 0.0f);

        const uint4* hv0 = (const uint4*)sh[warp][0][par];
        const uint4* hv1 = (const uint4*)sh[warp][1][par];
        #pragma unroll
        for (int q = 0; q < 4; q++) {
            const uint4 u = hv0[q];
            const uint4 v = hv1[q];
            rA0 = __hfma2(wr[4 * q],     H2(u.x), rA0);
            zA0 = __hfma2(wz[4 * q],     H2(u.x), zA0);
            nA0 = __hfma2(wn[4 * q],     H2(u.x), nA0);
            rB0 = __hfma2(wr[4 * q],     H2(v.x), rB0);
            zB0 = __hfma2(wz[4 * q],     H2(v.x), zB0);
            nB0 = __hfma2(wn[4 * q],     H2(v.x), nB0);
            rA1 = __hfma2(wr[4 * q + 1], H2(u.y), rA1);
            zA1 = __hfma2(wz[4 * q + 1], H2(u.y), zA1);
            nA1 = __hfma2(wn[4 * q + 1], H2(u.y), nA1);
            rB1 = __hfma2(wr[4 * q + 1], H2(v.y), rB1);
            zB1 = __hfma2(wz[4 * q + 1], H2(v.y), zB1);
            nB1 = __hfma2(wn[4 * q + 1], H2(v.y), nB1);
            rA0 = __hfma2(wr[4 * q + 2], H2(u.z), rA0);
            zA0 = __hfma2(wz[4 * q + 2], H2(u.z), zA0);
            nA0 = __hfma2(wn[4 * q + 2], H2(u.z), nA0);
            rB0 = __hfma2(wr[4 * q + 2], H2(v.z), rB0);
            zB0 = __hfma2(wz[4 * q + 2], H2(v.z), zB0);
            nB0 = __hfma2(wn[4 * q + 2], H2(v.z), nB0);
            rA1 = __hfma2(wr[4 * q + 3], H2(u.w), rA1);
            zA1 = __hfma2(wz[4 * q + 3], H2(u.w), zA1);
            nA1 = __hfma2(wn[4 * q + 3], H2(u.w), nA1);
            rB1 = __hfma2(wr[4 * q + 3], H2(v.w), rB1);
            zB1 = __hfma2(wz[4 * q + 3], H2(v.w), zB1);
            nB1 = __hfma2(wn[4 * q + 3], H2(v.w), nB1);
        }

        const float r0 = fsig(sum2(rin0) + h2sum(__hadd2(rA0, rA1)));
        const float r1 = fsig(sum2(rin1) + h2sum(__hadd2(rB0, rB1)));
        const float z0 = fsig(sum2(zin0) + h2sum(__hadd2(zA0, zA1)));
        const float z1 = fsig(sum2(zin1) + h2sum(__hadd2(zB0, zB1)));
        const float n0 = ftanh(sum2(xin0) + r0 * (bhn + h2sum(__hadd2(nA0, nA1))));
        const float n1 = ftanh(sum2(xin1) + r1 * (bhn + h2sum(__hadd2(nB0, nB1))));
        h0 = n0 + z0 * (h0 - n0);
        h1 = n1 + z1 * (h1 - n1);

        oA[(size_t)t * 2 * HH] = __float2half(h0);
        oB[(size_t)t * 2 * HH] = __float2half(h1);
        a0 = a1; a1 = a2;
        c0 = c1; c1 = c2;
    }
}

// ---------------------------------------------------------------------------
// Layer 1 input projection, packed u64 gate output. block 128, grid 1024.
// (unchanged from R14 best)
// ---------------------------------------------------------------------------
__global__ void __launch_bounds__(128) gru_l1_xg(
    const float* __restrict__ w_ih,   // [2,96,64]
    const float* __restrict__ b_ih)   // [2,96]
{
    __shared__ __align__(16) unsigned int sx[4][2][2][32];

    const int w = threadIdx.x >> 5;
    const int j = threadIdx.x & 31;

    const int task  = blockIdx.x * 4 + w;   // (b*2 + dir)*2 + chunkhalf
    const int chalf = task & 1;
    const int bd    = task >> 1;
    const int dir   = bd & 1;
    const int b     = bd >> 1;

    const u64* w64 = (const u64*)w_ih;
    __half2 wgr[32], wgz[32], wgn[32];
    {
        const int rb = (dir * GG + j) * 32;
        const int zb = (dir * GG + 32 + j) * 32;
        const int nb = (dir * GG + 64 + j) * 32;
        #pragma unroll
        for (int m = 0; m < 32; m++) {
            wgr[m] = u64_to_h2(w64[rb + m]);
            wgz[m] = u64_to_h2(w64[zb + m]);
            wgn[m] = u64_to_h2(w64[nb + m]);
        }
    }
    const float br = b_ih[dir * GG + j];
    const float bz = b_ih[dir * GG + 32 + j];
    const float bn = b_ih[dir * GG + 64 + j];

    const unsigned int* ib = (const unsigned int*)g_h1 + (size_t)b * TT * 32;
    u64* xo = g_xg + ((size_t)(dir * BB + b) * TT) * 32 + j;

    const int t0 = chalf * (TT / 2);
    unsigned int a0 = ib[(size_t)t0 * 32 + j];
    unsigned int a1 = ib[(size_t)(t0 + 1) * 32 + j];

    for (int s = 0; s < TT / 4; ++s) {
        const int t  = t0 + 2 * s;
        const int tn = (s == TT / 4 - 1) ? t : (t + 2);
        const unsigned int p0 = ib[(size_t)tn * 32 + j];
        const unsigned int p1 = ib[(size_t)(tn + 1) * 32 + j];

        const int par = s & 1;
        sx[w][par][0][j] = a0;
        sx[w][par][1][j] = a1;
        __syncwarp();

        __half2 R0, R1, Z0, Z1, N0, N1;
        __half2 R2, R3, Z2, Z3, N2, N3;
        R0 = R1 = Z0 = Z1 = N0 = N1 = __floats2half2_rn(0.0f, 0.0f);
        R2 = R3 = Z2 = Z3 = N2 = N3 = __floats2half2_rn(0.0f, 0.0f);

        const uint4* r0p = (const uint4*)&sx[w][par][0][0];
        const uint4* r1p = (const uint4*)&sx[w][par][1][0];
        #pragma unroll
        for (int q = 0; q < 8; q++) {
            const uint4 u = r0p[q];
            const uint4 v = r1p[q];
            R0 = __hfma2(wgr[4 * q],     H2(u.x), R0);
            Z0 = __hfma2(wgz[4 * q],     H2(u.x), Z0);
            N0 = __hfma2(wgn[4 * q],     H2(u.x), N0);
            R1 = __hfma2(wgr[4 * q + 1], H2(u.y), R1);
            Z1 = __hfma2(wgz[4 * q + 1], H2(u.y), Z1);
            N1 = __hfma2(wgn[4 * q + 1], H2(u.y), N1);
            R0 = __hfma2(wgr[4 * q + 2], H2(u.z), R0);
            Z0 = __hfma2(wgz[4 * q + 2], H2(u.z), Z0);
            N0 = __hfma2(wgn[4 * q + 2], H2(u.z), N0);
            R1 = __hfma2(wgr[4 * q + 3], H2(u.w), R1);
            Z1 = __hfma2(wgz[4 * q + 3], H2(u.w), Z1);
            N1 = __hfma2(wgn[4 * q + 3], H2(u.w), N1);

            R2 = __hfma2(wgr[4 * q],     H2(v.x), R2);
            Z2 = __hfma2(wgz[4 * q],     H2(v.x), Z2);
            N2 = __hfma2(wgn[4 * q],     H2(v.x), N2);
            R3 = __hfma2(wgr[4 * q + 1], H2(v.y), R3);
            Z3 = __hfma2(wgz[4 * q + 1], H2(v.y), Z3);
            N3 = __hfma2(wgn[4 * q + 1], H2(v.y), N3);
            R2 = __hfma2(wgr[4 * q + 2], H2(v.z), R2);
            Z2 = __hfma2(wgz[4 * q + 2], H2(v.z), Z2);
            N2 = __hfma2(wgn[4 * q + 2], H2(v.z), N2);
            R3 = __hfma2(wgr[4 * q + 3], H2(v.w), R3);
            Z3 = __hfma2(wgz[4 * q + 3], H2(v.w), Z3);
            N3 = __hfma2(wgn[4 * q + 3], H2(v.w), N3);
        }

        {
            const float rv = br + h2sum(__hadd2(R0, R1));
            const float zv = bz + h2sum(__hadd2(Z0, Z1));
            const float nv = bn + h2sum(__hadd2(N0, N1));
            const __half2 lo = __floats2half2_rn(rv, zv);
            const __half2 hi = __floats2half2_rn(nv, 0.0f);
            u64 pk;
            asm("mov.b64 %0, {%1, %2};" : "=l"(pk)
                : "r"(*(const unsigned int*)&lo), "r"(*(const unsigned int*)&hi));
            xo[(size_t)t * 32] = pk;
        }
        {
            const float rv = br + h2sum(__hadd2(R2, R3));
            const float zv = bz + h2sum(__hadd2(Z2, Z3));
            const float nv = bn + h2sum(__hadd2(N2, N3));
            const __half2 lo = __floats2half2_rn(rv, zv);
            const __half2 hi = __floats2half2_rn(nv, 0.0f);
            u64 pk;
            asm("mov.b64 %0, {%1, %2};" : "=l"(pk)
                : "r"(*(const unsigned int*)&lo), "r"(*(const unsigned int*)&hi));
            xo[(size_t)(t + 1) * 32] = pk;
        }
        a0 = p0; a1 = p1;
    }
}

// ---------------------------------------------------------------------------
// Layer 1 recurrence: TWO sequences per warp, shared weights, packed u64
// gate loads with prefetch depth 3, HW tanh. grid (B/4, 2), block 64.
// ---------------------------------------------------------------------------
__global__ void __launch_bounds__(64) gru_l1_rec(
    const float* __restrict__ w_hh,   // [2,96,32]
    const float* __restrict__ b_hh)   // [2,96]
{
    __shared__ __align__(16) __half sh[2][2][2][32];

    const int warp = threadIdx.x >> 5;
    const int j    = threadIdx.x & 31;
    const int dir  = blockIdx.y;
    const int b0   = blockIdx.x * 4 + warp * 2;

    const u64* w64 = (const u64*)w_hh;
    __half2 wr[16], wz[16], wn[16];
    {
        const int rb = (dir * GG + j) * 16;
        const int zb = (dir * GG + 32 + j) * 16;
        const int nb = (dir * GG + 64 + j) * 16;
        #pragma unroll
        for (int m = 0; m < 16; m++) {
            wr[m] = u64_to_h2(w64[rb + m]);
            wz[m] = u64_to_h2(w64[zb + m]);
            wn[m] = u64_to_h2(w64[nb + m]);
        }
    }
    const float brh = b_hh[dir * GG + j];
    const float bzh = b_hh[dir * GG + 32 + j];
    const float bhn = b_hh[dir * GG + 64 + j];

    float h0 = 0.0f, h1 = 0.0f;
    const int tstep = dir ? -1 : 1;
    int t = dir ? (TT - 1) : 0;

    const u64* xgA = g_xg + ((size_t)(dir * BB + b0) * TT) * 32 + j;
    const u64* xgB = xgA + (size_t)TT * 32;
    float* oA = g_out + (size_t)b0 * TT * 2 * HH + dir * HH + j;
    float* oB = oA + (size_t)TT * 2 * HH;

    u64 qa0 = xgA[(size_t)t * 32];
    u64 qa1 = xgA[(size_t)(t + tstep) * 32];
    u64 qa2 = xgA[(size_t)(t + 2 * tstep) * 32];
    u64 qb0 = xgB[(size_t)t * 32];
    u64 qb1 = xgB[(size_t)(t + tstep) * 32];
    u64 qb2 = xgB[(size_t)(t + 2 * tstep) * 32];

    for (int s = 0; s < TT; ++s, t += tstep) {
        int tp = t + 3 * tstep;
        tp = (tp < 0) ? 0 : ((tp >= TT) ? (TT - 1) : tp);
        const u64 qa3 = xgA[(size_t)tp * 32];
        const u64 qb3 = xgB[(size_t)tp * 32];

        const int par = s & 1;
        sh[warp][0][par][j] = __float2half(h0);
        sh[warp][1][par][j] = __float2half(h1);
        __syncwarp();

        unsigned int lo0u, hi0u, lo1u, hi1u;
        asm("mov.b64 {%0, %1}, %2;" : "=r"(lo0u), "=r"(hi0u) : "l"(qa0));
        asm("mov.b64 {%0, %1}, %2;" : "=r"(lo1u), "=r"(hi1u) : "l"(qb0));
        const float xr0 = __low2float(H2(lo0u));
        const float xz0 = __high2float(H2(lo0u));
        const float xn0 = __low2float(H2(hi0u));
        const float xr1 = __low2float(H2(lo1u));
        const float xz1 = __high2float(H2(lo1u));
        const float xn1 = __low2float(H2(hi1u));

        __half2 rA0, rA1, zA0, zA1, nA0, nA1;
        __half2 rB0, rB1, zB0, zB1, nB0, nB1;
        rA0 = rA1 = zA0 = zA1 = nA0 = nA1 = __floats2half2_rn(0.0f, 0.0f);
        rB0 = rB1 = zB0 = zB1 = nB0 = nB1 = __floats2half2_rn(0.0f, 0.0f);

        const uint4* hv0 = (const uint4*)sh[warp][0][par];
        const uint4* hv1 = (const uint4*)sh[warp][1][par];
        #pragma unroll
        for (int q = 0; q < 4; q++) {
            const uint4 u = hv0[q];
            const uint4 v = hv1[q];
            rA0 = __hfma2(wr[4 * q],     H2(u.x), rA0);
            zA0 = __hfma2(wz[4 * q],     H2(u.x), zA0);
            nA0 = __hfma2(wn[4 * q],     H2(u.x), nA0);
            rB0 = __hfma2(wr[4 * q],     H2(v.x), rB0);
            zB0 = __hfma2(wz[4 * q],     H2(v.x), zB0);
            nB0 = __hfma2(wn[4 * q],     H2(v.x), nB0);
            rA1 = __hfma2(wr[4 * q + 1], H2(u.y), rA1);
            zA1 = __hfma2(wz[4 * q + 1], H2(u.y), zA1);
            nA1 = __hfma2(wn[4 * q + 1], H2(u.y), nA1);
            rB1 = __hfma2(wr[4 * q + 1], H2(v.y), rB1);
            zB1 = __hfma2(wz[4 * q + 1], H2(v.y), zB1);
            nB1 = __hfma2(wn[4 * q + 1], H2(v.y), nB1);
            rA0 = __hfma2(wr[4 * q + 2], H2(u.z), rA0);
            zA0 = __hfma2(wz[4 * q + 2], H2(u.z), zA0);
            nA0 = __hfma2(wn[4 * q + 2], H2(u.z), nA0);
            rB0 = __hfma2(wr[4 * q + 2], H2(v.z), rB0);
            zB0 = __hfma2(wz[4 * q + 2], H2(v.z), zB0);
            nB0 = __hfma2(wn[4 * q + 2], H2(v.z), nB0);
            rA1 = __hfma2(wr[4 * q + 3], H2(u.w), rA1);
            zA1 = __hfma2(wz[4 * q + 3], H2(u.w), zA1);
            nA1 = __hfma2(wn[4 * q + 3], H2(u.w), nA1);
            rB1 = __hfma2(wr[4 * q + 3], H2(v.w), rB1);
            zB1 = __hfma2(wz[4 * q + 3], H2(v.w), zB1);
            nB1 = __hfma2(wn[4 * q + 3], H2(v.w), nB1);
        }

        const float r0 = fsig(xr0 + brh + h2sum(__hadd2(rA0, rA1)));
        const float r1 = fsig(xr1 + brh + h2sum(__hadd2(rB0, rB1)));
        const float z0 = fsig(xz0 + bzh + h2sum(__hadd2(zA0, zA1)));
        const float z1 = fsig(xz1 + bzh + h2sum(__hadd2(zB0, zB1)));
        const float n0 = ftanh(xn0 + r0 * (bhn + h2sum(__hadd2(nA0, nA1))));
        const float n1 = ftanh(xn1 + r1 * (bhn + h2sum(__hadd2(nB0, nB1))));
        h0 = n0 + z0 * (h0 - n0);
        h1 = n1 + z1 * (h1 - n1);

        oA[(size_t)t * 2 * HH] = h0;
        oB[(size_t)t * 2 * HH] = h1;
        qa0 = qa1; qa1 = qa2; qa2 = qa3;
        qb0 = qb1; qb1 = qb2; qb2 = qb3;
    }
}

// ---------------------------------------------------------------------------
// Epilogue: single-pass online-softmax attention pooling + sigmoid FC.
// ---------------------------------------------------------------------------
__global__ void __launch_bounds__(256) attn_fc_kernel(
    const float* __restrict__ attn_w,  // [1,64]
    const float* __restrict__ fc_w,    // [1,64]
    const float* __restrict__ fc_b,    // [1]
    float* __restrict__ y)             // [B,1]
{
    __shared__ float saw[64], sfw[64];
    __shared__ float sm[8], sz[8];
    __shared__ float sctx[8][64];

    const int b    = blockIdx.x;
    const int tid  = threadIdx.x;
    const int warp = tid >> 5;
    const int lane = tid & 31;

    if (tid < 64) {
        saw[tid] = attn_w[tid];
        sfw[tid] = fc_w[tid];
    }
    __syncthreads();

    const float aw0 = saw[lane], aw1 = saw[lane + 32];
    const float* ob = g_out + (size_t)b * TT * 64;

    float m = -INFINITY, Z = 0.0f, c0 = 0.0f, c1 = 0.0f;
    for (int t = warp; t < TT; t += 8) {
        const float* p = ob + (size_t)t * 64;
        const float q0 = p[lane];
        const float q1 = p[lane + 32];
        float v = q0 * aw0 + q1 * aw1;
        #pragma unroll
        for (int o = 16; o; o >>= 1) v += __shfl_xor_sync(0xffffffffu, v, o);
        const float mn = fmaxf(m, v);
        const float sc = __expf(m - mn);
        const float e  = __expf(v - mn);
        Z  = Z * sc + e;
        c0 = c0 * sc + e * q0;
        c1 = c1 * sc + e * q1;
        m = mn;
    }
    if (lane == 0) sm[warp] = m;
    __syncthreads();

    float M = sm[0];
    #pragma unroll
    for (int w = 1; w < 8; w++) M = fmaxf(M, sm[w]);
    const float sc = __expf(m - M);
    if (lane == 0) sz[warp] = Z * sc;
    sctx[warp][lane]      = c0 * sc;
    sctx[warp][lane + 32] = c1 * sc;
    __syncthreads();

    if (tid < 32) {
        float Zt = 0.0f, C0 = 0.0f, C1 = 0.0f;
        #pragma unroll
        for (int w = 0; w < 8; w++) {
            Zt += sz[w];
            C0 += sctx[w][lane];
            C1 += sctx[w][lane + 32];
        }
        float v = C0 * sfw[lane] + C1 * sfw[lane + 32];
        #pragma unroll
        for (int o = 16; o; o >>= 1) v += __shfl_xor_sync(0xffffffffu, v, o);
        if (lane == 0) {
            y[b] = fmaf(0.5f, ftanh(0.5f * (__fdividef(v, Zt) + fc_b[0])), 0.5f);
        }
    }
}

extern "C" void kernel_launch(void* const* d_in, const int* in_sizes, int n_in,
                              void* d_out, int out_size) {
    const float* x       = (const float*)d_in[0];
    const float* w_ih_l0 = (const float*)d_in[1];
    const float* w_hh_l0 = (const float*)d_in[2];
    const float* b_ih_l0 = (const float*)d_in[3];
    const float* b_hh_l0 = (const float*)d_in[4];
    const float* w_ih_l1 = (const float*)d_in[5];
    const float* w_hh_l1 = (const float*)d_in[6];
    const float* b_ih_l1 = (const float*)d_in[7];
    const float* b_hh_l1 = (const float*)d_in[8];
    const float* attn_w  = (const float*)d_in[9];
    // d_in[10] = attn_b (cancels in softmax)
    const float* fc_w    = (const float*)d_in[11];
    const float* fc_b    = (const float*)d_in[12];
    float* y = (float*)d_out;

    gru_l0    <<<dim3(BB / 4, 2), 64>>>(x, w_ih_l0, w_hh_l0, b_ih_l0, b_hh_l0);
    gru_l1_xg <<<(BB * 2 * 2) / 4, 128>>>(w_ih_l1, b_ih_l1);
    gru_l1_rec<<<dim3(BB / 4, 2), 64>>>(w_hh_l1, b_hh_l1);
    attn_fc_kernel<<<BB, 256>>>(attn_w, fc_w, fc_b, y);
}